// round 3
// baseline (speedup 1.0000x reference)
#include <cuda_runtime.h>
#include <cstdint>

// Haar 2x2 wavelet: in (16,32,512,512) f32 -> out (16,128,256,256) f32
// out[b][0*32+c] = pooled, [1*32+c] = diff_h, [2*32+c] = diff_v, [3*32+c] = diff_d
//
// Pure streaming: 512 MiB in + 512 MiB out, each line touched once.
// R2 change: 2x work per thread (MLP 4->8 front-batched LDG.128) + .cs
// streaming hints on all loads/stores (evict-first, no L2 retention value).

#define B_  16
#define C_  32
#define H_  512
#define W_  512
#define HO_ 256
#define WO_ 256

__device__ __forceinline__ float4 ldcs4(const float* p) {
    return __ldcs(reinterpret_cast<const float4*>(p));
}
__device__ __forceinline__ void stcs4(float* p, float4 v) {
    __stcs(reinterpret_cast<float4*>(p), v);
}

__global__ __launch_bounds__(256) void haar_kernel(
    const float* __restrict__ x, float* __restrict__ out)
{
    // One thread = 8 output pixels (2x float4) at (bc, h, w8*8 .. w8*8+7)
    // total threads = B*C*HO*(WO/8) = 16*32*256*32 = 4,194,304
    const uint32_t t = blockIdx.x * blockDim.x + threadIdx.x;

    const uint32_t w8  = t & 31u;          // WO/8 = 32
    uint32_t tmp       = t >> 5;
    const uint32_t h   = tmp & 255u;       // HO = 256
    const uint32_t bc  = tmp >> 8;         // 0..511 (b*C + c)

    // ---- input loads: rows 2h, 2h+1, cols 16*w8 .. 16*w8+15 ----
    const float* row0 = x + ((size_t)bc * (H_ * W_)) + (size_t)(2u * h) * W_ + w8 * 16u;
    const float* row1 = row0 + W_;

    // 8 independent LDG.128s, front-batched for MLP
    const float4 t0 = ldcs4(row0);
    const float4 t1 = ldcs4(row0 + 4);
    const float4 t2 = ldcs4(row0 + 8);
    const float4 t3 = ldcs4(row0 + 12);
    const float4 b0 = ldcs4(row1);
    const float4 b1 = ldcs4(row1 + 4);
    const float4 b2 = ldcs4(row1 + 8);
    const float4 b3 = ldcs4(row1 + 12);

    // ---- output addressing ----
    const uint32_t b_idx = bc >> 5;        // /32
    const uint32_t ch    = bc & 31u;       // %32
    const size_t plane = (size_t)HO_ * WO_;
    float* obase = out + ((size_t)b_idx * (4 * C_) + ch) * plane
                       + (size_t)h * WO_ + w8 * 8u;

    // helper: process one (top,bottom) float4 pair -> 2 outputs per plane
    // pairs within a float4: (x,y) and (z,w)
    #define HAAR2(T, Bt, po, dhio, dvo, ddo)                         \
    {                                                                \
        const float a0 = T.x, e0 = T.y, c0 = Bt.x, d0 = Bt.y;        \
        const float a1 = T.z, e1 = T.w, c1 = Bt.z, d1 = Bt.w;        \
        po.x  = (a0 + e0 + c0 + d0) * 0.25f;                         \
        po.y  = (a1 + e1 + c1 + d1) * 0.25f;                         \
        dhio.x = (a0 + e0 - c0 - d0) * 0.5f;                         \
        dhio.y = (a1 + e1 - c1 - d1) * 0.5f;                         \
        dvo.x  = (a0 + c0 - e0 - d0) * 0.5f;                         \
        dvo.y  = (a1 + c1 - e1 - d1) * 0.5f;                         \
        ddo.x  = a0 - e0 - c0 + d0;                                  \
        ddo.y  = a1 - e1 - c1 + d1;                                  \
    }

    float2 p0, p1, p2, p3, h0, h1, h2, h3, v0, v1, v2, v3, g0, g1, g2, g3;
    HAAR2(t0, b0, p0, h0, v0, g0)
    HAAR2(t1, b1, p1, h1, v1, g1)
    HAAR2(t2, b2, p2, h2, v2, g2)
    HAAR2(t3, b3, p3, h3, v3, g3)
    #undef HAAR2

    float4 P0 = make_float4(p0.x, p0.y, p1.x, p1.y);
    float4 P1 = make_float4(p2.x, p2.y, p3.x, p3.y);
    float4 Hh0 = make_float4(h0.x, h0.y, h1.x, h1.y);
    float4 Hh1 = make_float4(h2.x, h2.y, h3.x, h3.y);
    float4 V0 = make_float4(v0.x, v0.y, v1.x, v1.y);
    float4 V1 = make_float4(v2.x, v2.y, v3.x, v3.y);
    float4 D0 = make_float4(g0.x, g0.y, g1.x, g1.y);
    float4 D1 = make_float4(g2.x, g2.y, g3.x, g3.y);

    stcs4(obase,                      P0);
    stcs4(obase + 4,                  P1);
    stcs4(obase + 1 * C_ * plane,     Hh0);
    stcs4(obase + 1 * C_ * plane + 4, Hh1);
    stcs4(obase + 2 * C_ * plane,     V0);
    stcs4(obase + 2 * C_ * plane + 4, V1);
    stcs4(obase + 3 * C_ * plane,     D0);
    stcs4(obase + 3 * C_ * plane + 4, D1);
}

extern "C" void kernel_launch(void* const* d_in, const int* in_sizes, int n_in,
                              void* d_out, int out_size)
{
    const float* x = (const float*)d_in[0];
    float* out = (float*)d_out;

    const uint32_t total_threads = B_ * C_ * HO_ * (WO_ / 8);  // 4,194,304
    const uint32_t block = 256;
    const uint32_t grid = total_threads / block;               // 16384

    haar_kernel<<<grid, block>>>(x, out);
}

// round 4
// speedup vs baseline: 1.0507x; 1.0507x over previous
#include <cuda_runtime.h>
#include <cstdint>

// Haar 2x2 wavelet: in (16,32,512,512) f32 -> out (16,128,256,256) f32
// out[b][0*32+c] = pooled, [1*32+c] = diff_h, [2*32+c] = diff_v, [3*32+c] = diff_d
//
// R4: R0 structure (MLP=4, 32 regs, full occupancy) + .cs evict-first on
// LOADS only (input lines are single-touch; keep L2 capacity for the
// store write-back stream). Stores remain default STG.128.

#define B_  16
#define C_  32
#define H_  512
#define W_  512
#define HO_ 256
#define WO_ 256

__global__ __launch_bounds__(256) void haar_kernel(
    const float* __restrict__ x, float* __restrict__ out)
{
    // One thread = 4 output pixels (float4 wide) at (bc, h, w4*4..w4*4+3)
    // total threads = B*C*HO*(WO/4) = 16*32*256*64 = 8,388,608
    const uint32_t t = blockIdx.x * blockDim.x + threadIdx.x;

    const uint32_t w4  = t & 63u;          // WO/4 = 64
    uint32_t tmp       = t >> 6;
    const uint32_t h   = tmp & 255u;       // HO = 256
    const uint32_t bc  = tmp >> 8;         // 0..511 (b*C + c)

    // ---- input loads: rows 2h and 2h+1, cols 8*w4 .. 8*w4+7 ----
    const float* row0 = x + ((size_t)bc * (H_ * W_)) + (size_t)(2u * h) * W_ + w4 * 8u;
    const float* row1 = row0 + W_;

    const float4 t0 = __ldcs(reinterpret_cast<const float4*>(row0));
    const float4 t1 = __ldcs(reinterpret_cast<const float4*>(row0 + 4));
    const float4 b0 = __ldcs(reinterpret_cast<const float4*>(row1));
    const float4 b1 = __ldcs(reinterpret_cast<const float4*>(row1 + 4));

    // pairs: (a,b) from top row, (c,d) from bottom row
    const float a0 = t0.x, bb0 = t0.y, c0 = b0.x, d0 = b0.y;
    const float a1 = t0.z, bb1 = t0.w, c1 = b0.z, d1 = b0.w;
    const float a2 = t1.x, bb2 = t1.y, c2 = b1.x, d2 = b1.y;
    const float a3 = t1.z, bb3 = t1.w, c3 = b1.z, d3 = b1.w;

    float4 pooled, dh, dv, dd;

    pooled.x = (a0 + bb0 + c0 + d0) * 0.25f;
    pooled.y = (a1 + bb1 + c1 + d1) * 0.25f;
    pooled.z = (a2 + bb2 + c2 + d2) * 0.25f;
    pooled.w = (a3 + bb3 + c3 + d3) * 0.25f;

    dh.x = (a0 + bb0 - c0 - d0) * 0.5f;
    dh.y = (a1 + bb1 - c1 - d1) * 0.5f;
    dh.z = (a2 + bb2 - c2 - d2) * 0.5f;
    dh.w = (a3 + bb3 - c3 - d3) * 0.5f;

    dv.x = (a0 + c0 - bb0 - d0) * 0.5f;
    dv.y = (a1 + c1 - bb1 - d1) * 0.5f;
    dv.z = (a2 + c2 - bb2 - d2) * 0.5f;
    dv.w = (a3 + c3 - bb3 - d3) * 0.5f;

    dd.x = a0 - bb0 - c0 + d0;
    dd.y = a1 - bb1 - c1 + d1;
    dd.z = a2 - bb2 - c2 + d2;
    dd.w = a3 - bb3 - c3 + d3;

    // ---- output stores ----
    const uint32_t b_idx = bc >> 5;        // /32
    const uint32_t ch    = bc & 31u;       // %32
    // out[b][g*32+ch][h][w]; plane = HO*WO = 65536
    const size_t plane = (size_t)HO_ * WO_;
    float* obase = out + ((size_t)b_idx * (4 * C_) + ch) * plane
                       + (size_t)h * WO_ + w4 * 4u;

    *reinterpret_cast<float4*>(obase)                   = pooled;  // group 0
    *reinterpret_cast<float4*>(obase + 1 * C_ * plane)  = dh;      // group 1
    *reinterpret_cast<float4*>(obase + 2 * C_ * plane)  = dv;      // group 2
    *reinterpret_cast<float4*>(obase + 3 * C_ * plane)  = dd;      // group 3
}

extern "C" void kernel_launch(void* const* d_in, const int* in_sizes, int n_in,
                              void* d_out, int out_size)
{
    const float* x = (const float*)d_in[0];
    float* out = (float*)d_out;

    const uint32_t total_threads = B_ * C_ * HO_ * (WO_ / 4);  // 8,388,608
    const uint32_t block = 256;
    const uint32_t grid = total_threads / block;               // 32768

    haar_kernel<<<grid, block>>>(x, out);
}

// round 5
// speedup vs baseline: 1.0658x; 1.0144x over previous
#include <cuda_runtime.h>
#include <cstdint>

// Haar 2x2 wavelet: in (16,32,512,512) f32 -> out (16,128,256,256) f32
// out[b][0*32+c] = pooled, [1*32+c] = diff_h, [2*32+c] = diff_v, [3*32+c] = diff_d
//
// FINAL (R0 config): pure streaming kernel at the mixed read+write HBM
// ceiling (~86% of 8 TB/s). Tested and rejected: 2x per-thread MLP
// (regs 32->48, occupancy loss, -7% DRAM), .cs evict-first hints on
// loads and/or stores (-1..-9% DRAM). Default caching + MLP=4 + 32 regs
// + full-occupancy 256-thread blocks is the measured optimum.

#define B_  16
#define C_  32
#define H_  512
#define W_  512
#define HO_ 256
#define WO_ 256

__global__ __launch_bounds__(256) void haar_kernel(
    const float* __restrict__ x, float* __restrict__ out)
{
    // One thread = 4 output pixels (float4 wide) at (bc, h, w4*4..w4*4+3)
    // total threads = B*C*HO*(WO/4) = 16*32*256*64 = 8,388,608
    const uint32_t t = blockIdx.x * blockDim.x + threadIdx.x;

    const uint32_t w4  = t & 63u;          // WO/4 = 64
    uint32_t tmp       = t >> 6;
    const uint32_t h   = tmp & 255u;       // HO = 256
    const uint32_t bc  = tmp >> 8;         // 0..511 (b*C + c)

    // ---- input loads: rows 2h and 2h+1, cols 8*w4 .. 8*w4+7 ----
    const float* row0 = x + ((size_t)bc * (H_ * W_)) + (size_t)(2u * h) * W_ + w4 * 8u;
    const float* row1 = row0 + W_;

    const float4 t0 = *reinterpret_cast<const float4*>(row0);
    const float4 t1 = *reinterpret_cast<const float4*>(row0 + 4);
    const float4 b0 = *reinterpret_cast<const float4*>(row1);
    const float4 b1 = *reinterpret_cast<const float4*>(row1 + 4);

    // pairs: (a,b) from top row, (c,d) from bottom row
    const float a0 = t0.x, bb0 = t0.y, c0 = b0.x, d0 = b0.y;
    const float a1 = t0.z, bb1 = t0.w, c1 = b0.z, d1 = b0.w;
    const float a2 = t1.x, bb2 = t1.y, c2 = b1.x, d2 = b1.y;
    const float a3 = t1.z, bb3 = t1.w, c3 = b1.z, d3 = b1.w;

    float4 pooled, dh, dv, dd;

    pooled.x = (a0 + bb0 + c0 + d0) * 0.25f;
    pooled.y = (a1 + bb1 + c1 + d1) * 0.25f;
    pooled.z = (a2 + bb2 + c2 + d2) * 0.25f;
    pooled.w = (a3 + bb3 + c3 + d3) * 0.25f;

    dh.x = (a0 + bb0 - c0 - d0) * 0.5f;
    dh.y = (a1 + bb1 - c1 - d1) * 0.5f;
    dh.z = (a2 + bb2 - c2 - d2) * 0.5f;
    dh.w = (a3 + bb3 - c3 - d3) * 0.5f;

    dv.x = (a0 + c0 - bb0 - d0) * 0.5f;
    dv.y = (a1 + c1 - bb1 - d1) * 0.5f;
    dv.z = (a2 + c2 - bb2 - d2) * 0.5f;
    dv.w = (a3 + c3 - bb3 - d3) * 0.5f;

    dd.x = a0 - bb0 - c0 + d0;
    dd.y = a1 - bb1 - c1 + d1;
    dd.z = a2 - bb2 - c2 + d2;
    dd.w = a3 - bb3 - c3 + d3;

    // ---- output stores ----
    const uint32_t b_idx = bc >> 5;        // /32
    const uint32_t ch    = bc & 31u;       // %32
    // out[b][g*32+ch][h][w]; plane = HO*WO = 65536
    const size_t plane = (size_t)HO_ * WO_;
    float* obase = out + ((size_t)b_idx * (4 * C_) + ch) * plane
                       + (size_t)h * WO_ + w4 * 4u;

    *reinterpret_cast<float4*>(obase)                   = pooled;  // group 0
    *reinterpret_cast<float4*>(obase + 1 * C_ * plane)  = dh;      // group 1
    *reinterpret_cast<float4*>(obase + 2 * C_ * plane)  = dv;      // group 2
    *reinterpret_cast<float4*>(obase + 3 * C_ * plane)  = dd;      // group 3
}

extern "C" void kernel_launch(void* const* d_in, const int* in_sizes, int n_in,
                              void* d_out, int out_size)
{
    const float* x = (const float*)d_in[0];
    float* out = (float*)d_out;

    const uint32_t total_threads = B_ * C_ * HO_ * (WO_ / 4);  // 8,388,608
    const uint32_t block = 256;
    const uint32_t grid = total_threads / block;               // 32768

    haar_kernel<<<grid, block>>>(x, out);
}